// round 3
// baseline (speedup 1.0000x reference)
#include <cuda_runtime.h>
#include <cstdint>
#include <cstddef>

// ---------------------------------------------------------------------------
// Bidirectional LSTM, encoder folded into input weights.
// 512 independent sequences (256 batch x 2 dirs), 4 per CTA, 128 CTAs.
//
// Round 3 restructure: split gates = Wx.x + Wh.h. Phase 1 = Wh.h (serial
// part, full 64-k dot per thread, no partial reduction). Phase 2 = epilogue
// OVERLAPPED with Wx.x for step t+1 (independent of h), results staged in a
// 2-slot smem ring. FMA work per step unchanged; stalls now filled.
// ---------------------------------------------------------------------------

#define T_STEPS 4096
#define B_TOT   256
#define HID     64
#define KIN     60
#define KPAD    128
#define NGATES  256

__device__ float g_Wcomb[2][NGATES][KPAD];   // [dir][row][k]: k<60 = Wx, 60..123 = Wh
__device__ float g_biasc[2][NGATES];
__device__ float g_cfin[2][B_TOT][HID];

__device__ __forceinline__ unsigned long long pack2(float lo, float hi) {
    unsigned long long u;
    asm("mov.b64 %0, {%1, %2};" : "=l"(u) : "f"(lo), "f"(hi));
    return u;
}
__device__ __forceinline__ void unpack2(unsigned long long u, float& lo, float& hi) {
    asm("mov.b64 {%0, %1}, %2;" : "=f"(lo), "=f"(hi) : "l"(u));
}
__device__ __forceinline__ void ffma2(unsigned long long& d,
                                      unsigned long long a,
                                      unsigned long long b) {
    asm("fma.rn.f32x2 %0, %1, %2, %0;" : "+l"(d) : "l"(a), "l"(b));
}

__device__ __forceinline__ float fast_sigmoid(float x) {
    return __fdividef(1.0f, 1.0f + __expf(-x));
}
__device__ __forceinline__ float fast_tanh(float x) {
    return 1.0f - __fdividef(2.0f, __expf(2.0f * x) + 1.0f);
}

// ---------------------------------------------------------------------------
__global__ void prep_kernel(const float* __restrict__ W_enc,
                            const float* __restrict__ b_enc,
                            const float* __restrict__ W_ih_f,
                            const float* __restrict__ W_hh_f,
                            const float* __restrict__ b_f,
                            const float* __restrict__ W_ih_b,
                            const float* __restrict__ W_hh_b,
                            const float* __restrict__ b_b) {
    const int dir = blockIdx.x;
    const int r   = threadIdx.x;
    const float* W_ih = dir ? W_ih_b : W_ih_f;
    const float* W_hh = dir ? W_hh_b : W_hh_f;
    const float* bv   = dir ? b_b    : b_f;

    float wih[32];
#pragma unroll
    for (int e = 0; e < 32; e++) wih[e] = W_ih[r * 32 + e];

    for (int k = 0; k < KIN; k++) {
        float s = 0.0f;
#pragma unroll
        for (int e = 0; e < 32; e++) s += wih[e] * W_enc[e * 60 + k];
        g_Wcomb[dir][r][k] = s;
    }
#pragma unroll
    for (int k = 0; k < HID; k++) g_Wcomb[dir][r][KIN + k] = W_hh[r * HID + k];
#pragma unroll
    for (int k = KIN + HID; k < KPAD; k++) g_Wcomb[dir][r][k] = 0.0f;

    float s = bv[r];
#pragma unroll
    for (int e = 0; e < 32; e++) s += wih[e] * b_enc[e];
    g_biasc[dir][r] = s;
}

// dummy pads so ncu -s 5 -c 1 lands on lstm_kernel
__global__ void pad_kernel() {}

// ---------------------------------------------------------------------------
// 128 CTAs x 256 threads. CTA = (dir, 4 batch seqs). Thread = one gate row.
// ---------------------------------------------------------------------------
__global__ void __launch_bounds__(256, 1)
lstm_kernel(const float* __restrict__ cin) {
    const int dir = blockIdx.x >> 6;
    const int bg  = blockIdx.x & 63;
    const int tid = threadIdx.x;

    __shared__ __align__(16) float hbuf[4][HID];          // current h per seq
    __shared__ __align__(16) float xr[3][4][64];          // x input ring (pad 60->64)
    __shared__ float gsm[4][NGATES];                      // Wh.h gates
    __shared__ float gxr[2][4][NGATES];                   // Wx.x gate ring

    // weights for this gate row: Wx (30 pairs), Wh (32 pairs)
    unsigned long long wx[30], wh[32];
    {
        const float* wr = &g_Wcomb[dir][tid][0];
#pragma unroll
        for (int i = 0; i < 30; i++) {
            float2 a = *reinterpret_cast<const float2*>(wr + 2 * i);
            wx[i] = pack2(a.x, a.y);
        }
#pragma unroll
        for (int i = 0; i < 32; i++) {
            float2 a = *reinterpret_cast<const float2*>(wr + KIN + 2 * i);
            wh[i] = pack2(a.x, a.y);
        }
    }
    const unsigned long long binit = pack2(g_biasc[dir][tid], 0.0f);

    const int s_ep = tid >> 6;    // epilogue seq
    const int j_ep = tid & 63;    // epilogue hidden unit
    hbuf[s_ep][j_ep] = 0.0f;      // h0 = 0

    // x loader mapping: threads 0..239 own one (seq, feature)
    const int  xs   = tid / KIN;
    const int  xk   = tid - xs * KIN;
    const bool xact = (tid < 4 * KIN);
    const float* cbase = cin + ((size_t)(bg * 4 + xs) * T_STEPS) * KIN + xk;
#define TMAP(t) (dir ? (T_STEPS - 1 - (t)) : (t))

    if (xact) xr[0][xs][xk] = __ldg(cbase + (size_t)TMAP(0) * KIN);
    __syncthreads();

    // prologue: Wx.x for t=0 -> gxr[0]
    {
        unsigned long long a0 = binit, a1 = binit, a2 = binit, a3 = binit;
        const float* xb = &xr[0][0][0];
#pragma unroll
        for (int ch = 0; ch < 15; ch++) {
            const ulonglong2 v0 = *reinterpret_cast<const ulonglong2*>(xb + 0 * 64 + 4 * ch);
            const ulonglong2 v1 = *reinterpret_cast<const ulonglong2*>(xb + 1 * 64 + 4 * ch);
            const ulonglong2 v2 = *reinterpret_cast<const ulonglong2*>(xb + 2 * 64 + 4 * ch);
            const ulonglong2 v3 = *reinterpret_cast<const ulonglong2*>(xb + 3 * 64 + 4 * ch);
            ffma2(a0, wx[2 * ch], v0.x); ffma2(a0, wx[2 * ch + 1], v0.y);
            ffma2(a1, wx[2 * ch], v1.x); ffma2(a1, wx[2 * ch + 1], v1.y);
            ffma2(a2, wx[2 * ch], v2.x); ffma2(a2, wx[2 * ch + 1], v2.y);
            ffma2(a3, wx[2 * ch], v3.x); ffma2(a3, wx[2 * ch + 1], v3.y);
        }
        float l, h;
        unpack2(a0, l, h); gxr[0][0][tid] = l + h;
        unpack2(a1, l, h); gxr[0][1][tid] = l + h;
        unpack2(a2, l, h); gxr[0][2][tid] = l + h;
        unpack2(a3, l, h); gxr[0][3][tid] = l + h;
    }
    if (xact) xr[1][xs][xk] = __ldg(cbase + (size_t)TMAP(1) * KIN);
    float cst = 0.0f;
    __syncthreads();

    for (int t = 0; t < T_STEPS; t++) {
        // ---- phase 1: Wh . h  (serial-critical part) ----
        {
            unsigned long long a0 = 0ull, a1 = 0ull, a2 = 0ull, a3 = 0ull;
            const float* hb = &hbuf[0][0];
#pragma unroll
            for (int ch = 0; ch < 16; ch++) {
                const ulonglong2 v0 = *reinterpret_cast<const ulonglong2*>(hb + 0 * HID + 4 * ch);
                const ulonglong2 v1 = *reinterpret_cast<const ulonglong2*>(hb + 1 * HID + 4 * ch);
                const ulonglong2 v2 = *reinterpret_cast<const ulonglong2*>(hb + 2 * HID + 4 * ch);
                const ulonglong2 v3 = *reinterpret_cast<const ulonglong2*>(hb + 3 * HID + 4 * ch);
                ffma2(a0, wh[2 * ch], v0.x); ffma2(a0, wh[2 * ch + 1], v0.y);
                ffma2(a1, wh[2 * ch], v1.x); ffma2(a1, wh[2 * ch + 1], v1.y);
                ffma2(a2, wh[2 * ch], v2.x); ffma2(a2, wh[2 * ch + 1], v2.y);
                ffma2(a3, wh[2 * ch], v3.x); ffma2(a3, wh[2 * ch + 1], v3.y);
            }
            float l, h;
            unpack2(a0, l, h); gsm[0][tid] = l + h;
            unpack2(a1, l, h); gsm[1][tid] = l + h;
            unpack2(a2, l, h); gsm[2][tid] = l + h;
            unpack2(a3, l, h); gsm[3][tid] = l + h;
        }
        // prefetch x[t+2] into register (DRAM latency hidden across a full step)
        float xnext = 0.0f;
        const bool ldp = xact && (t + 2) < T_STEPS;
        if (ldp) xnext = __ldg(cbase + (size_t)TMAP(t + 2) * KIN);
        __syncthreads();   // BAR1: gsm ready, hbuf reads done

        // ---- phase 2: epilogue  +  Wx.x for step t+1 (independent, fills stalls) ----
        {
            const float* gx = &gxr[t & 1][s_ep][0];
            const float* gh = &gsm[s_ep][0];
            const float gi = gh[j_ep]           + gx[j_ep];
            const float gf = gh[HID + j_ep]     + gx[HID + j_ep];
            const float gg = gh[2 * HID + j_ep] + gx[2 * HID + j_ep];
            const float go = gh[3 * HID + j_ep] + gx[3 * HID + j_ep];

            const float ig = fast_sigmoid(gi);
            const float fg = fast_sigmoid(gf);
            const float og = fast_sigmoid(go);
            const float gt = fast_tanh(gg);
            cst = fg * cst + ig * gt;
            hbuf[s_ep][j_ep] = og * fast_tanh(cst);
        }
        if (t + 1 < T_STEPS) {
            const int rs = (t + 1) % 3;
            unsigned long long a0 = binit, a1 = binit, a2 = binit, a3 = binit;
            const float* xb = &xr[rs][0][0];
#pragma unroll
            for (int ch = 0; ch < 15; ch++) {
                const ulonglong2 v0 = *reinterpret_cast<const ulonglong2*>(xb + 0 * 64 + 4 * ch);
                const ulonglong2 v1 = *reinterpret_cast<const ulonglong2*>(xb + 1 * 64 + 4 * ch);
                const ulonglong2 v2 = *reinterpret_cast<const ulonglong2*>(xb + 2 * 64 + 4 * ch);
                const ulonglong2 v3 = *reinterpret_cast<const ulonglong2*>(xb + 3 * 64 + 4 * ch);
                ffma2(a0, wx[2 * ch], v0.x); ffma2(a0, wx[2 * ch + 1], v0.y);
                ffma2(a1, wx[2 * ch], v1.x); ffma2(a1, wx[2 * ch + 1], v1.y);
                ffma2(a2, wx[2 * ch], v2.x); ffma2(a2, wx[2 * ch + 1], v2.y);
                ffma2(a3, wx[2 * ch], v3.x); ffma2(a3, wx[2 * ch + 1], v3.y);
            }
            const int gs = (t + 1) & 1;
            float l, h;
            unpack2(a0, l, h); gxr[gs][0][tid] = l + h;
            unpack2(a1, l, h); gxr[gs][1][tid] = l + h;
            unpack2(a2, l, h); gxr[gs][2][tid] = l + h;
            unpack2(a3, l, h); gxr[gs][3][tid] = l + h;
        }
        if (ldp) xr[(t + 2) % 3][xs][xk] = xnext;
        __syncthreads();   // BAR2: h, gxr, xr published
    }

    g_cfin[dir][bg * 4 + s_ep][j_ep] = cst;
}

// ---------------------------------------------------------------------------
__global__ void final_kernel(const float* __restrict__ W_fin,
                             const float* __restrict__ b_fin,
                             float* __restrict__ out) {
    const int b = threadIdx.x;
    float a0 = b_fin[0], a1 = b_fin[1], a2 = b_fin[2];
#pragma unroll
    for (int j = 0; j < HID; j++) {
        const float cf = g_cfin[0][b][j];
        a0 += W_fin[0 * 128 + j] * cf;
        a1 += W_fin[1 * 128 + j] * cf;
        a2 += W_fin[2 * 128 + j] * cf;
    }
#pragma unroll
    for (int j = 0; j < HID; j++) {
        const float cb = g_cfin[1][b][j];
        a0 += W_fin[0 * 128 + 64 + j] * cb;
        a1 += W_fin[1 * 128 + 64 + j] * cb;
        a2 += W_fin[2 * 128 + 64 + j] * cb;
    }
    out[b * 3 + 0] = a0;
    out[b * 3 + 1] = a1;
    out[b * 3 + 2] = a2;
}

extern "C" void kernel_launch(void* const* d_in, const int* in_sizes, int n_in,
                              void* d_out, int out_size) {
    (void)in_sizes; (void)n_in; (void)out_size;
    const float* c      = (const float*)d_in[0];
    const float* W_enc  = (const float*)d_in[1];
    const float* b_enc  = (const float*)d_in[2];
    const float* W_ih_f = (const float*)d_in[3];
    const float* W_hh_f = (const float*)d_in[4];
    const float* b_f    = (const float*)d_in[5];
    const float* W_ih_b = (const float*)d_in[6];
    const float* W_hh_b = (const float*)d_in[7];
    const float* b_b    = (const float*)d_in[8];
    const float* W_fin  = (const float*)d_in[9];
    const float* b_fin  = (const float*)d_in[10];
    float* out = (float*)d_out;

    prep_kernel<<<2, 256>>>(W_enc, b_enc, W_ih_f, W_hh_f, b_f, W_ih_b, W_hh_b, b_b);
    pad_kernel<<<1, 32>>>();
    pad_kernel<<<1, 32>>>();
    lstm_kernel<<<128, 256>>>(c);
    final_kernel<<<1, 256>>>(W_fin, b_fin, out);
}

// round 4
// speedup vs baseline: 1.2602x; 1.2602x over previous
#include <cuda_runtime.h>
#include <cstdint>
#include <cstddef>

// ---------------------------------------------------------------------------
// Bidirectional LSTM, encoder folded into input weights.
// 512 independent sequences (256 batch x 2 dirs), 4 per CTA, 128 CTAs.
//
// Round 4: warp-specialized lockstep.
//   Warps 4-7 (Wh group): thread = 2 gate rows x full 64 h-dims (R=2 -> each
//     broadcast LDS.128 feeds 4 FFMA2; no k-split, no partial reduction).
//   Warps 0-3 (Wx group): thread = 2 gate rows x 60 x-dims, computes the
//     x-projection for step t+1 (independent of h) concurrently with Wh.
//   Epilogue: 1 LSTM cell per thread (256 cells), 8 scalar LDS + 6 MUFU.
//   2 __syncthreads per step. FMA pipe is the intended limiter.
// ---------------------------------------------------------------------------

#define T_STEPS 4096
#define B_TOT   256
#define HID     64
#define KIN     60
#define KPAD    128
#define NGATES  256

__device__ float g_Wcomb[2][NGATES][KPAD];   // [dir][row][k]: k<60 = Wx, 60..123 = Wh
__device__ float g_biasc[2][NGATES];
__device__ float g_cfin[2][B_TOT][HID];

__device__ __forceinline__ unsigned long long pack2(float lo, float hi) {
    unsigned long long u;
    asm("mov.b64 %0, {%1, %2};" : "=l"(u) : "f"(lo), "f"(hi));
    return u;
}
__device__ __forceinline__ void unpack2(unsigned long long u, float& lo, float& hi) {
    asm("mov.b64 {%0, %1}, %2;" : "=f"(lo), "=f"(hi) : "l"(u));
}
__device__ __forceinline__ void ffma2(unsigned long long& d,
                                      unsigned long long a,
                                      unsigned long long b) {
    asm("fma.rn.f32x2 %0, %1, %2, %0;" : "+l"(d) : "l"(a), "l"(b));
}

__device__ __forceinline__ float fast_sigmoid(float x) {
    return __fdividef(1.0f, 1.0f + __expf(-x));
}
__device__ __forceinline__ float fast_tanh(float x) {
    return 1.0f - __fdividef(2.0f, __expf(2.0f * x) + 1.0f);
}

// ---------------------------------------------------------------------------
__global__ void prep_kernel(const float* __restrict__ W_enc,
                            const float* __restrict__ b_enc,
                            const float* __restrict__ W_ih_f,
                            const float* __restrict__ W_hh_f,
                            const float* __restrict__ b_f,
                            const float* __restrict__ W_ih_b,
                            const float* __restrict__ W_hh_b,
                            const float* __restrict__ b_b) {
    const int dir = blockIdx.x;
    const int r   = threadIdx.x;
    const float* W_ih = dir ? W_ih_b : W_ih_f;
    const float* W_hh = dir ? W_hh_b : W_hh_f;
    const float* bv   = dir ? b_b    : b_f;

    float wih[32];
#pragma unroll
    for (int e = 0; e < 32; e++) wih[e] = W_ih[r * 32 + e];

    for (int k = 0; k < KIN; k++) {
        float s = 0.0f;
#pragma unroll
        for (int e = 0; e < 32; e++) s += wih[e] * W_enc[e * 60 + k];
        g_Wcomb[dir][r][k] = s;
    }
#pragma unroll
    for (int k = 0; k < HID; k++) g_Wcomb[dir][r][KIN + k] = W_hh[r * HID + k];
#pragma unroll
    for (int k = KIN + HID; k < KPAD; k++) g_Wcomb[dir][r][k] = 0.0f;

    float s = bv[r];
#pragma unroll
    for (int e = 0; e < 32; e++) s += wih[e] * b_enc[e];
    g_biasc[dir][r] = s;
}

// dummy pads so ncu -s 5 -c 1 lands on lstm_kernel
__global__ void pad_kernel() {}

// ---------------------------------------------------------------------------
// 128 CTAs x 256 threads. CTA = (dir, 4 batch seqs).
// ---------------------------------------------------------------------------
__global__ void __launch_bounds__(256, 1)
lstm_kernel(const float* __restrict__ cin) {
    const int dir = blockIdx.x >> 6;
    const int bg  = blockIdx.x & 63;
    const int tid = threadIdx.x;

    __shared__ __align__(16) float hbuf[4][HID];     // h_t per seq
    __shared__ __align__(16) float xr[3][4][HID];    // x ring (60 used, 4 pad)
    __shared__ float gsm[4][NGATES];                 // Wh.h gates (step t)
    __shared__ float gxr[2][4][NGATES];              // Wx.x + bias gate ring

    const bool is_wh = (tid >= 128);     // warps 4-7: recurrent (hi arbiter prio)
    const int  gid   = is_wh ? (tid - 128) : tid;   // 0..127 within group
    const int  r0    = 2 * gid;          // this thread's 2 gate rows

#define TMAP(t) (dir ? (T_STEPS - 1 - (t)) : (t))

    // ---- per-group weight registers ----
    unsigned long long w0[32], w1[32];   // row r0 / r0+1 packed pairs
    int nch;                             // chunk count (16 for Wh, 15 for Wx)
    if (is_wh) {
        const float* a = &g_Wcomb[dir][r0][KIN];
        const float* b = &g_Wcomb[dir][r0 + 1][KIN];
#pragma unroll
        for (int i = 0; i < 32; i++) {
            float2 p = *reinterpret_cast<const float2*>(a + 2 * i);
            float2 q = *reinterpret_cast<const float2*>(b + 2 * i);
            w0[i] = pack2(p.x, p.y);
            w1[i] = pack2(q.x, q.y);
        }
        nch = 16;
    } else {
        const float* a = &g_Wcomb[dir][r0][0];
        const float* b = &g_Wcomb[dir][r0 + 1][0];
#pragma unroll
        for (int i = 0; i < 30; i++) {
            float2 p = *reinterpret_cast<const float2*>(a + 2 * i);
            float2 q = *reinterpret_cast<const float2*>(b + 2 * i);
            w0[i] = pack2(p.x, p.y);
            w1[i] = pack2(q.x, q.y);
        }
        w0[30] = w0[31] = w1[30] = w1[31] = 0ull;
        nch = 15;
    }
    (void)nch;

    // bias init (only used by Wx accumulators)
    const unsigned long long bi0 = pack2(g_biasc[dir][r0], 0.0f);
    const unsigned long long bi1 = pack2(g_biasc[dir][r0 + 1], 0.0f);

    // epilogue mapping: 1 cell per thread
    const int s_ep = tid >> 6;
    const int j_ep = tid & 63;
    float cst = 0.0f;
    hbuf[s_ep][j_ep] = 0.0f;   // h0 = 0

    // x loader mapping (Wx threads only): elems e = gid, gid+128 of 240
    const int  e0s = gid / KIN,         e0k = gid - e0s * KIN;
    const int  e1  = gid + 128;
    const int  e1s = e1 / KIN,          e1k = e1 - e1s * KIN;
    const bool le1 = (e1 < 4 * KIN);
    const float* cb0 = cin + ((size_t)(bg * 4 + e0s) * T_STEPS) * KIN + e0k;
    const float* cb1 = cin + ((size_t)(bg * 4 + e1s) * T_STEPS) * KIN + e1k;

    // zero the x pad columns once
    if (!is_wh && gid < 3 * 4) {   // 12 threads x (slot, seq) pairs
        const int sl = gid >> 2, sq = gid & 3;
        xr[sl][sq][60] = xr[sl][sq][61] = xr[sl][sq][62] = xr[sl][sq][63] = 0.0f;
    }

    // prologue: fill xr[0], xr[1]; seed LDG for x(2)
    float xa = 0.0f, xb = 0.0f;
    if (!is_wh) {
        xr[0][e0s][e0k] = __ldg(cb0 + (size_t)TMAP(0) * KIN);
        if (le1) xr[0][e1s][e1k] = __ldg(cb1 + (size_t)TMAP(0) * KIN);
        xr[1][e0s][e0k] = __ldg(cb0 + (size_t)TMAP(1) * KIN);
        if (le1) xr[1][e1s][e1k] = __ldg(cb1 + (size_t)TMAP(1) * KIN);
        xa = __ldg(cb0 + (size_t)TMAP(2) * KIN);
        if (le1) xb = __ldg(cb1 + (size_t)TMAP(2) * KIN);
    }
    __syncthreads();

    // prologue: gx(0) -> gxr[0]
    if (!is_wh) {
        unsigned long long a0 = bi0, a1 = bi0, a2 = bi0, a3 = bi0;
        unsigned long long c0 = bi1, c1 = bi1, c2 = bi1, c3 = bi1;
        const float* xb0 = &xr[0][0][0];
#pragma unroll
        for (int ch = 0; ch < 15; ch++) {
            const ulonglong2 v0 = *reinterpret_cast<const ulonglong2*>(xb0 + 0 * HID + 4 * ch);
            const ulonglong2 v1 = *reinterpret_cast<const ulonglong2*>(xb0 + 1 * HID + 4 * ch);
            const ulonglong2 v2 = *reinterpret_cast<const ulonglong2*>(xb0 + 2 * HID + 4 * ch);
            const ulonglong2 v3 = *reinterpret_cast<const ulonglong2*>(xb0 + 3 * HID + 4 * ch);
            ffma2(a0, w0[2 * ch], v0.x); ffma2(a0, w0[2 * ch + 1], v0.y);
            ffma2(c0, w1[2 * ch], v0.x); ffma2(c0, w1[2 * ch + 1], v0.y);
            ffma2(a1, w0[2 * ch], v1.x); ffma2(a1, w0[2 * ch + 1], v1.y);
            ffma2(c1, w1[2 * ch], v1.x); ffma2(c1, w1[2 * ch + 1], v1.y);
            ffma2(a2, w0[2 * ch], v2.x); ffma2(a2, w0[2 * ch + 1], v2.y);
            ffma2(c2, w1[2 * ch], v2.x); ffma2(c2, w1[2 * ch + 1], v2.y);
            ffma2(a3, w0[2 * ch], v3.x); ffma2(a3, w0[2 * ch + 1], v3.y);
            ffma2(c3, w1[2 * ch], v3.x); ffma2(c3, w1[2 * ch + 1], v3.y);
        }
        float l, h, l2, h2;
        unpack2(a0, l, h); unpack2(c0, l2, h2);
        *reinterpret_cast<float2*>(&gxr[0][0][r0]) = make_float2(l + h, l2 + h2);
        unpack2(a1, l, h); unpack2(c1, l2, h2);
        *reinterpret_cast<float2*>(&gxr[0][1][r0]) = make_float2(l + h, l2 + h2);
        unpack2(a2, l, h); unpack2(c2, l2, h2);
        *reinterpret_cast<float2*>(&gxr[0][2][r0]) = make_float2(l + h, l2 + h2);
        unpack2(a3, l, h); unpack2(c3, l2, h2);
        *reinterpret_cast<float2*>(&gxr[0][3][r0]) = make_float2(l + h, l2 + h2);
    }
    __syncthreads();

    for (int t = 0; t < T_STEPS; t++) {
        // ================= phase A =================
        if (is_wh) {
            // gates_h(t) = Wh . h_t
            unsigned long long a0 = 0ull, a1 = 0ull, a2 = 0ull, a3 = 0ull;
            unsigned long long c0 = 0ull, c1 = 0ull, c2 = 0ull, c3 = 0ull;
            const float* hb = &hbuf[0][0];
#pragma unroll
            for (int ch = 0; ch < 16; ch++) {
                const ulonglong2 v0 = *reinterpret_cast<const ulonglong2*>(hb + 0 * HID + 4 * ch);
                const ulonglong2 v1 = *reinterpret_cast<const ulonglong2*>(hb + 1 * HID + 4 * ch);
                const ulonglong2 v2 = *reinterpret_cast<const ulonglong2*>(hb + 2 * HID + 4 * ch);
                const ulonglong2 v3 = *reinterpret_cast<const ulonglong2*>(hb + 3 * HID + 4 * ch);
                ffma2(a0, w0[2 * ch], v0.x); ffma2(a0, w0[2 * ch + 1], v0.y);
                ffma2(c0, w1[2 * ch], v0.x); ffma2(c0, w1[2 * ch + 1], v0.y);
                ffma2(a1, w0[2 * ch], v1.x); ffma2(a1, w0[2 * ch + 1], v1.y);
                ffma2(c1, w1[2 * ch], v1.x); ffma2(c1, w1[2 * ch + 1], v1.y);
                ffma2(a2, w0[2 * ch], v2.x); ffma2(a2, w0[2 * ch + 1], v2.y);
                ffma2(c2, w1[2 * ch], v2.x); ffma2(c2, w1[2 * ch + 1], v2.y);
                ffma2(a3, w0[2 * ch], v3.x); ffma2(a3, w0[2 * ch + 1], v3.y);
                ffma2(c3, w1[2 * ch], v3.x); ffma2(c3, w1[2 * ch + 1], v3.y);
            }
            float l, h, l2, h2;
            unpack2(a0, l, h); unpack2(c0, l2, h2);
            *reinterpret_cast<float2*>(&gsm[0][r0]) = make_float2(l + h, l2 + h2);
            unpack2(a1, l, h); unpack2(c1, l2, h2);
            *reinterpret_cast<float2*>(&gsm[1][r0]) = make_float2(l + h, l2 + h2);
            unpack2(a2, l, h); unpack2(c2, l2, h2);
            *reinterpret_cast<float2*>(&gsm[2][r0]) = make_float2(l + h, l2 + h2);
            unpack2(a3, l, h); unpack2(c3, l2, h2);
            *reinterpret_cast<float2*>(&gsm[3][r0]) = make_float2(l + h, l2 + h2);
        } else {
            // gates_x(t+1) = Wx . x_{t+1} + bias  (independent of h_t)
            if (t + 1 < T_STEPS) {
                const int rs = (t + 1) % 3;
                unsigned long long a0 = bi0, a1 = bi0, a2 = bi0, a3 = bi0;
                unsigned long long c0 = bi1, c1 = bi1, c2 = bi1, c3 = bi1;
                const float* xb0 = &xr[rs][0][0];
#pragma unroll
                for (int ch = 0; ch < 15; ch++) {
                    const ulonglong2 v0 = *reinterpret_cast<const ulonglong2*>(xb0 + 0 * HID + 4 * ch);
                    const ulonglong2 v1 = *reinterpret_cast<const ulonglong2*>(xb0 + 1 * HID + 4 * ch);
                    const ulonglong2 v2 = *reinterpret_cast<const ulonglong2*>(xb0 + 2 * HID + 4 * ch);
                    const ulonglong2 v3 = *reinterpret_cast<const ulonglong2*>(xb0 + 3 * HID + 4 * ch);
                    ffma2(a0, w0[2 * ch], v0.x); ffma2(a0, w0[2 * ch + 1], v0.y);
                    ffma2(c0, w1[2 * ch], v0.x); ffma2(c0, w1[2 * ch + 1], v0.y);
                    ffma2(a1, w0[2 * ch], v1.x); ffma2(a1, w0[2 * ch + 1], v1.y);
                    ffma2(c1, w1[2 * ch], v1.x); ffma2(c1, w1[2 * ch + 1], v1.y);
                    ffma2(a2, w0[2 * ch], v2.x); ffma2(a2, w0[2 * ch + 1], v2.y);
                    ffma2(c2, w1[2 * ch], v2.x); ffma2(c2, w1[2 * ch + 1], v2.y);
                    ffma2(a3, w0[2 * ch], v3.x); ffma2(a3, w0[2 * ch + 1], v3.y);
                    ffma2(c3, w1[2 * ch], v3.x); ffma2(c3, w1[2 * ch + 1], v3.y);
                }
                const int gs = (t + 1) & 1;
                float l, h, l2, h2;
                unpack2(a0, l, h); unpack2(c0, l2, h2);
                *reinterpret_cast<float2*>(&gxr[gs][0][r0]) = make_float2(l + h, l2 + h2);
                unpack2(a1, l, h); unpack2(c1, l2, h2);
                *reinterpret_cast<float2*>(&gxr[gs][1][r0]) = make_float2(l + h, l2 + h2);
                unpack2(a2, l, h); unpack2(c2, l2, h2);
                *reinterpret_cast<float2*>(&gxr[gs][2][r0]) = make_float2(l + h, l2 + h2);
                unpack2(a3, l, h); unpack2(c3, l2, h2);
                *reinterpret_cast<float2*>(&gxr[gs][3][r0]) = make_float2(l + h, l2 + h2);
            }
            // stage x(t+2) from registers (LDG issued at step t-1); fetch x(t+3)
            if (t + 2 < T_STEPS) {
                const int ws = (t + 2) % 3;
                xr[ws][e0s][e0k] = xa;
                if (le1) xr[ws][e1s][e1k] = xb;
            }
            if (t + 3 < T_STEPS) {
                xa = __ldg(cb0 + (size_t)TMAP(t + 3) * KIN);
                if (le1) xb = __ldg(cb1 + (size_t)TMAP(t + 3) * KIN);
            }
        }
        __syncthreads();   // BAR1: gsm(t), gxr[(t+1)&1], xr staged

        // ================= phase B: epilogue (1 cell/thread) =================
        {
            const float* gh = &gsm[s_ep][0];
            const float* gx = &gxr[t & 1][s_ep][0];
            const float gi = gh[j_ep]           + gx[j_ep];
            const float gf = gh[HID + j_ep]     + gx[HID + j_ep];
            const float gg = gh[2 * HID + j_ep] + gx[2 * HID + j_ep];
            const float go = gh[3 * HID + j_ep] + gx[3 * HID + j_ep];

            const float ig = fast_sigmoid(gi);
            const float fg = fast_sigmoid(gf);
            const float og = fast_sigmoid(go);
            const float gt = fast_tanh(gg);
            cst = fg * cst + ig * gt;
            hbuf[s_ep][j_ep] = og * fast_tanh(cst);
        }
        __syncthreads();   // BAR2: h_{t+1} published
    }

    g_cfin[dir][bg * 4 + s_ep][j_ep] = cst;
}

// ---------------------------------------------------------------------------
__global__ void final_kernel(const float* __restrict__ W_fin,
                             const float* __restrict__ b_fin,
                             float* __restrict__ out) {
    const int b = threadIdx.x;
    float a0 = b_fin[0], a1 = b_fin[1], a2 = b_fin[2];
#pragma unroll
    for (int j = 0; j < HID; j++) {
        const float cf = g_cfin[0][b][j];
        a0 += W_fin[0 * 128 + j] * cf;
        a1 += W_fin[1 * 128 + j] * cf;
        a2 += W_fin[2 * 128 + j] * cf;
    }
#pragma unroll
    for (int j = 0; j < HID; j++) {
        const float cb = g_cfin[1][b][j];
        a0 += W_fin[0 * 128 + 64 + j] * cb;
        a1 += W_fin[1 * 128 + 64 + j] * cb;
        a2 += W_fin[2 * 128 + 64 + j] * cb;
    }
    out[b * 3 + 0] = a0;
    out[b * 3 + 1] = a1;
    out[b * 3 + 2] = a2;
}

extern "C" void kernel_launch(void* const* d_in, const int* in_sizes, int n_in,
                              void* d_out, int out_size) {
    (void)in_sizes; (void)n_in; (void)out_size;
    const float* c      = (const float*)d_in[0];
    const float* W_enc  = (const float*)d_in[1];
    const float* b_enc  = (const float*)d_in[2];
    const float* W_ih_f = (const float*)d_in[3];
    const float* W_hh_f = (const float*)d_in[4];
    const float* b_f    = (const float*)d_in[5];
    const float* W_ih_b = (const float*)d_in[6];
    const float* W_hh_b = (const float*)d_in[7];
    const float* b_b    = (const float*)d_in[8];
    const float* W_fin  = (const float*)d_in[9];
    const float* b_fin  = (const float*)d_in[10];
    float* out = (float*)d_out;

    prep_kernel<<<2, 256>>>(W_enc, b_enc, W_ih_f, W_hh_f, b_f, W_ih_b, W_hh_b, b_b);
    pad_kernel<<<1, 32>>>();
    pad_kernel<<<1, 32>>>();
    lstm_kernel<<<128, 256>>>(c);
    final_kernel<<<1, 256>>>(W_fin, b_fin, out);
}

// round 5
// speedup vs baseline: 1.3202x; 1.0477x over previous
#include <cuda_runtime.h>
#include <cstdint>
#include <cstddef>

// ---------------------------------------------------------------------------
// Bidirectional LSTM, encoder folded into input weights.
// 512 independent sequences (256 batch x 2 dirs), 4 per CTA, 128 CTAs.
//
// Round 5: fully decoupled producer/consumer warp groups via NAMED barriers.
//   Wh group (warps 4-7): Wh.h matmul -> bar1(128) -> epilogue (2 cells/thr)
//     -> bar1(128). Never waits for Wx except on the gxr ring.
//   Wx group (warps 0-3): free-runs computing gx(t+1) = Wx.x_{t+1} + bias into
//     a 2-slot ring; paired full/empty named barriers (arrive/sync, count 256).
//   No __syncthreads in the loop. FMA pipe (992 cyc/SMSP/step) is the limiter.
// ---------------------------------------------------------------------------

#define T_STEPS 4096
#define B_TOT   256
#define HID     64
#define KIN     60
#define KPAD    128
#define NGATES  256

__device__ float g_Wcomb[2][NGATES][KPAD];   // [dir][row][k]: k<60 = Wx, 60..123 = Wh
__device__ float g_biasc[2][NGATES];
__device__ float g_cfin[2][B_TOT][HID];

__device__ __forceinline__ unsigned long long pack2(float lo, float hi) {
    unsigned long long u;
    asm("mov.b64 %0, {%1, %2};" : "=l"(u) : "f"(lo), "f"(hi));
    return u;
}
__device__ __forceinline__ void unpack2(unsigned long long u, float& lo, float& hi) {
    asm("mov.b64 {%0, %1}, %2;" : "=f"(lo), "=f"(hi) : "l"(u));
}
__device__ __forceinline__ void ffma2(unsigned long long& d,
                                      unsigned long long a,
                                      unsigned long long b) {
    asm("fma.rn.f32x2 %0, %1, %2, %0;" : "+l"(d) : "l"(a), "l"(b));
}

__device__ __forceinline__ float fast_sigmoid(float x) {
    return __fdividef(1.0f, 1.0f + __expf(-x));
}
__device__ __forceinline__ float fast_tanh(float x) {
    return 1.0f - __fdividef(2.0f, __expf(2.0f * x) + 1.0f);
}

#define BSYNC(id, cnt) asm volatile("bar.sync %0, %1;"   :: "r"(id), "r"(cnt) : "memory")
#define BARRV(id, cnt) asm volatile("bar.arrive %0, %1;" :: "r"(id), "r"(cnt) : "memory")

// ---------------------------------------------------------------------------
__global__ void prep_kernel(const float* __restrict__ W_enc,
                            const float* __restrict__ b_enc,
                            const float* __restrict__ W_ih_f,
                            const float* __restrict__ W_hh_f,
                            const float* __restrict__ b_f,
                            const float* __restrict__ W_ih_b,
                            const float* __restrict__ W_hh_b,
                            const float* __restrict__ b_b) {
    const int dir = blockIdx.x;
    const int r   = threadIdx.x;
    const float* W_ih = dir ? W_ih_b : W_ih_f;
    const float* W_hh = dir ? W_hh_b : W_hh_f;
    const float* bv   = dir ? b_b    : b_f;

    float wih[32];
#pragma unroll
    for (int e = 0; e < 32; e++) wih[e] = W_ih[r * 32 + e];

    for (int k = 0; k < KIN; k++) {
        float s = 0.0f;
#pragma unroll
        for (int e = 0; e < 32; e++) s += wih[e] * W_enc[e * 60 + k];
        g_Wcomb[dir][r][k] = s;
    }
#pragma unroll
    for (int k = 0; k < HID; k++) g_Wcomb[dir][r][KIN + k] = W_hh[r * HID + k];
#pragma unroll
    for (int k = KIN + HID; k < KPAD; k++) g_Wcomb[dir][r][k] = 0.0f;

    float s = bv[r];
#pragma unroll
    for (int e = 0; e < 32; e++) s += wih[e] * b_enc[e];
    g_biasc[dir][r] = s;
}

// dummy pads so ncu -s 5 -c 1 lands on lstm_kernel
__global__ void pad_kernel() {}

// ---------------------------------------------------------------------------
// 128 CTAs x 256 threads. CTA = (dir, 4 batch seqs).
// Named barriers: 1 = Wh internal; 2/3 = full[slot]; 4/5 = empty[slot];
//                 6 = Wx internal (xr ring).
// ---------------------------------------------------------------------------
__global__ void __launch_bounds__(256, 1)
lstm_kernel(const float* __restrict__ cin) {
    const int dir = blockIdx.x >> 6;
    const int bg  = blockIdx.x & 63;
    const int tid = threadIdx.x;

    __shared__ __align__(16) float hbuf[4][HID];     // h_t per seq (Wh-private)
    __shared__ __align__(16) float xr[3][4][HID];    // x ring (Wx-private)
    __shared__ __align__(8)  float gsm[4][NGATES];   // Wh.h gates (Wh-private)
    __shared__ __align__(8)  float gxr[2][4][NGATES];// gx ring (Wx -> Wh)

    const bool is_wh = (tid >= 128);
    const int  gid   = tid & 127;
    const int  r0    = 2 * gid;

#define TMAP(t) (dir ? (T_STEPS - 1 - (t)) : (t))

    // registers shared across the branch join
    unsigned long long w0[32], w1[32];
    unsigned long long bi0 = 0ull, bi1 = 0ull;
    float xa = 0.0f, xb2 = 0.0f;

    // epilogue/cell mapping (Wh only)
    const int j_c  = gid & 63;
    const int s1   = gid >> 6;        // 0..1
    const int s2   = s1 + 2;          // 2..3

    // x loader mapping (Wx only)
    const int  e0s = gid / KIN,  e0k = gid - e0s * KIN;
    const int  e1  = gid + 128;
    const int  e1s = e1 / KIN,   e1k = e1 - e1s * KIN;
    const bool le1 = (e1 < 4 * KIN);
    const float* cb0 = cin + ((size_t)(bg * 4 + e0s) * T_STEPS) * KIN + e0k;
    const float* cb1 = cin + ((size_t)(bg * 4 + e1s) * T_STEPS) * KIN + e1k;

    // ---------------- prologue (convergent) ----------------
    if (is_wh) {
        const float* a = &g_Wcomb[dir][r0][KIN];
        const float* b = &g_Wcomb[dir][r0 + 1][KIN];
#pragma unroll
        for (int i = 0; i < 32; i++) {
            float2 p = *reinterpret_cast<const float2*>(a + 2 * i);
            float2 q = *reinterpret_cast<const float2*>(b + 2 * i);
            w0[i] = pack2(p.x, p.y);
            w1[i] = pack2(q.x, q.y);
        }
        hbuf[s1][j_c] = 0.0f;
        hbuf[s2][j_c] = 0.0f;
    } else {
        const float* a = &g_Wcomb[dir][r0][0];
        const float* b = &g_Wcomb[dir][r0 + 1][0];
#pragma unroll
        for (int i = 0; i < 30; i++) {
            float2 p = *reinterpret_cast<const float2*>(a + 2 * i);
            float2 q = *reinterpret_cast<const float2*>(b + 2 * i);
            w0[i] = pack2(p.x, p.y);
            w1[i] = pack2(q.x, q.y);
        }
        w0[30] = w0[31] = w1[30] = w1[31] = 0ull;
        bi0 = pack2(g_biasc[dir][r0], 0.0f);
        bi1 = pack2(g_biasc[dir][r0 + 1], 0.0f);

        // zero x pad columns (all 3 slots, 4 seqs, cols 60..63)
        if (gid < 48) {
            const int sl = gid >> 4, q = gid & 15;
            xr[sl][q >> 2][60 + (q & 3)] = 0.0f;
        }
        // fill xr slots 0..2 with x(0..2); stage x(3) in regs
        xr[0][e0s][e0k] = __ldg(cb0 + (size_t)TMAP(0) * KIN);
        if (le1) xr[0][e1s][e1k] = __ldg(cb1 + (size_t)TMAP(0) * KIN);
        xr[1][e0s][e0k] = __ldg(cb0 + (size_t)TMAP(1) * KIN);
        if (le1) xr[1][e1s][e1k] = __ldg(cb1 + (size_t)TMAP(1) * KIN);
        xr[2][e0s][e0k] = __ldg(cb0 + (size_t)TMAP(2) * KIN);
        if (le1) xr[2][e1s][e1k] = __ldg(cb1 + (size_t)TMAP(2) * KIN);
        xa = __ldg(cb0 + (size_t)TMAP(3) * KIN);
        if (le1) xb2 = __ldg(cb1 + (size_t)TMAP(3) * KIN);
    }
    __syncthreads();

    // ---------------- main loops (divergent, named-barrier coupled) --------
    if (is_wh) {
        float cs1 = 0.0f, cs2 = 0.0f;
        for (int t = 0; t < T_STEPS; t++) {
            // ---- Wh . h(t) ----
            unsigned long long a0 = 0ull, a1 = 0ull, a2 = 0ull, a3 = 0ull;
            unsigned long long c0 = 0ull, c1 = 0ull, c2 = 0ull, c3 = 0ull;
            const float* hb = &hbuf[0][0];
#pragma unroll
            for (int ch = 0; ch < 16; ch++) {
                const ulonglong2 v0 = *reinterpret_cast<const ulonglong2*>(hb + 0 * HID + 4 * ch);
                const ulonglong2 v1 = *reinterpret_cast<const ulonglong2*>(hb + 1 * HID + 4 * ch);
                const ulonglong2 v2 = *reinterpret_cast<const ulonglong2*>(hb + 2 * HID + 4 * ch);
                const ulonglong2 v3 = *reinterpret_cast<const ulonglong2*>(hb + 3 * HID + 4 * ch);
                ffma2(a0, w0[2 * ch], v0.x); ffma2(a0, w0[2 * ch + 1], v0.y);
                ffma2(c0, w1[2 * ch], v0.x); ffma2(c0, w1[2 * ch + 1], v0.y);
                ffma2(a1, w0[2 * ch], v1.x); ffma2(a1, w0[2 * ch + 1], v1.y);
                ffma2(c1, w1[2 * ch], v1.x); ffma2(c1, w1[2 * ch + 1], v1.y);
                ffma2(a2, w0[2 * ch], v2.x); ffma2(a2, w0[2 * ch + 1], v2.y);
                ffma2(c2, w1[2 * ch], v2.x); ffma2(c2, w1[2 * ch + 1], v2.y);
                ffma2(a3, w0[2 * ch], v3.x); ffma2(a3, w0[2 * ch + 1], v3.y);
                ffma2(c3, w1[2 * ch], v3.x); ffma2(c3, w1[2 * ch + 1], v3.y);
            }
            {
                float l, h, l2, h2;
                unpack2(a0, l, h); unpack2(c0, l2, h2);
                *reinterpret_cast<float2*>(&gsm[0][r0]) = make_float2(l + h, l2 + h2);
                unpack2(a1, l, h); unpack2(c1, l2, h2);
                *reinterpret_cast<float2*>(&gsm[1][r0]) = make_float2(l + h, l2 + h2);
                unpack2(a2, l, h); unpack2(c2, l2, h2);
                *reinterpret_cast<float2*>(&gsm[2][r0]) = make_float2(l + h, l2 + h2);
                unpack2(a3, l, h); unpack2(c3, l2, h2);
                *reinterpret_cast<float2*>(&gsm[3][r0]) = make_float2(l + h, l2 + h2);
            }
            BSYNC(1, 128);                 // gsm complete within Wh group
            BSYNC(2 + (t & 1), 256);       // full[t&1]: gx(t) ready

            // ---- epilogue: 2 cells per thread ----
            {
                const float* gh1 = &gsm[s1][0];
                const float* gx1 = &gxr[t & 1][s1][0];
                const float* gh2 = &gsm[s2][0];
                const float* gx2 = &gxr[t & 1][s2][0];

                const float gi1 = gh1[j_c]       + gx1[j_c];
                const float gf1 = gh1[64 + j_c]  + gx1[64 + j_c];
                const float gg1 = gh1[128 + j_c] + gx1[128 + j_c];
                const float go1 = gh1[192 + j_c] + gx1[192 + j_c];
                const float gi2 = gh2[j_c]       + gx2[j_c];
                const float gf2 = gh2[64 + j_c]  + gx2[64 + j_c];
                const float gg2 = gh2[128 + j_c] + gx2[128 + j_c];
                const float go2 = gh2[192 + j_c] + gx2[192 + j_c];

                const float ig1 = fast_sigmoid(gi1);
                const float ig2 = fast_sigmoid(gi2);
                const float fg1 = fast_sigmoid(gf1);
                const float fg2 = fast_sigmoid(gf2);
                const float gt1 = fast_tanh(gg1);
                const float gt2 = fast_tanh(gg2);
                const float og1 = fast_sigmoid(go1);
                const float og2 = fast_sigmoid(go2);

                cs1 = fg1 * cs1 + ig1 * gt1;
                cs2 = fg2 * cs2 + ig2 * gt2;
                hbuf[s1][j_c] = og1 * fast_tanh(cs1);
                hbuf[s2][j_c] = og2 * fast_tanh(cs2);
            }
            BARRV(4 + (t & 1), 256);       // empty[t&1]: gx slot consumed
            BSYNC(1, 128);                 // h(t+1) complete within Wh group
        }
        g_cfin[dir][bg * 4 + s1][j_c] = cs1;
        g_cfin[dir][bg * 4 + s2][j_c] = cs2;
    } else {
        int sl = 0;   // xr read/write slot = n % 3
        for (int n = 0; n < T_STEPS; n++) {
            if (n >= 2) BSYNC(4 + (n & 1), 256);   // empty[n&1]: slot reusable

            // ---- gx(n) = Wx . x(n) + bias ----
            unsigned long long a0 = bi0, a1 = bi0, a2 = bi0, a3 = bi0;
            unsigned long long c0 = bi1, c1 = bi1, c2 = bi1, c3 = bi1;
            const float* xb0 = &xr[sl][0][0];
#pragma unroll
            for (int ch = 0; ch < 15; ch++) {
                const ulonglong2 v0 = *reinterpret_cast<const ulonglong2*>(xb0 + 0 * HID + 4 * ch);
                const ulonglong2 v1 = *reinterpret_cast<const ulonglong2*>(xb0 + 1 * HID + 4 * ch);
                const ulonglong2 v2 = *reinterpret_cast<const ulonglong2*>(xb0 + 2 * HID + 4 * ch);
                const ulonglong2 v3 = *reinterpret_cast<const ulonglong2*>(xb0 + 3 * HID + 4 * ch);
                ffma2(a0, w0[2 * ch], v0.x); ffma2(a0, w0[2 * ch + 1], v0.y);
                ffma2(c0, w1[2 * ch], v0.x); ffma2(c0, w1[2 * ch + 1], v0.y);
                ffma2(a1, w0[2 * ch], v1.x); ffma2(a1, w0[2 * ch + 1], v1.y);
                ffma2(c1, w1[2 * ch], v1.x); ffma2(c1, w1[2 * ch + 1], v1.y);
                ffma2(a2, w0[2 * ch], v2.x); ffma2(a2, w0[2 * ch + 1], v2.y);
                ffma2(c2, w1[2 * ch], v2.x); ffma2(c2, w1[2 * ch + 1], v2.y);
                ffma2(a3, w0[2 * ch], v3.x); ffma2(a3, w0[2 * ch + 1], v3.y);
                ffma2(c3, w1[2 * ch], v3.x); ffma2(c3, w1[2 * ch + 1], v3.y);
            }
            {
                const int gs = n & 1;
                float l, h, l2, h2;
                unpack2(a0, l, h); unpack2(c0, l2, h2);
                *reinterpret_cast<float2*>(&gxr[gs][0][r0]) = make_float2(l + h, l2 + h2);
                unpack2(a1, l, h); unpack2(c1, l2, h2);
                *reinterpret_cast<float2*>(&gxr[gs][1][r0]) = make_float2(l + h, l2 + h2);
                unpack2(a2, l, h); unpack2(c2, l2, h2);
                *reinterpret_cast<float2*>(&gxr[gs][2][r0]) = make_float2(l + h, l2 + h2);
                unpack2(a3, l, h); unpack2(c3, l2, h2);
                *reinterpret_cast<float2*>(&gxr[gs][3][r0]) = make_float2(l + h, l2 + h2);
            }
            BARRV(2 + (n & 1), 256);   // full[n&1]: gx(n) published
            BSYNC(6, 128);             // all Wx reads of xr[sl] done

            if (n + 3 < T_STEPS) {     // stage x(n+3) into the freed slot
                xr[sl][e0s][e0k] = xa;
                if (le1) xr[sl][e1s][e1k] = xb2;
            }
            if (n + 4 < T_STEPS) {     // fetch x(n+4) (consumed next iter)
                xa = __ldg(cb0 + (size_t)TMAP(n + 4) * KIN);
                if (le1) xb2 = __ldg(cb1 + (size_t)TMAP(n + 4) * KIN);
            }
            sl = (sl == 2) ? 0 : sl + 1;
        }
    }
}

// ---------------------------------------------------------------------------
__global__ void final_kernel(const float* __restrict__ W_fin,
                             const float* __restrict__ b_fin,
                             float* __restrict__ out) {
    const int b = threadIdx.x;
    float a0 = b_fin[0], a1 = b_fin[1], a2 = b_fin[2];
#pragma unroll
    for (int j = 0; j < HID; j++) {
        const float cf = g_cfin[0][b][j];
        a0 += W_fin[0 * 128 + j] * cf;
        a1 += W_fin[1 * 128 + j] * cf;
        a2 += W_fin[2 * 128 + j] * cf;
    }
#pragma unroll
    for (int j = 0; j < HID; j++) {
        const float cb = g_cfin[1][b][j];
        a0 += W_fin[0 * 128 + 64 + j] * cb;
        a1 += W_fin[1 * 128 + 64 + j] * cb;
        a2 += W_fin[2 * 128 + 64 + j] * cb;
    }
    out[b * 3 + 0] = a0;
    out[b * 3 + 1] = a1;
    out[b * 3 + 2] = a2;
}

extern "C" void kernel_launch(void* const* d_in, const int* in_sizes, int n_in,
                              void* d_out, int out_size) {
    (void)in_sizes; (void)n_in; (void)out_size;
    const float* c      = (const float*)d_in[0];
    const float* W_enc  = (const float*)d_in[1];
    const float* b_enc  = (const float*)d_in[2];
    const float* W_ih_f = (const float*)d_in[3];
    const float* W_hh_f = (const float*)d_in[4];
    const float* b_f    = (const float*)d_in[5];
    const float* W_ih_b = (const float*)d_in[6];
    const float* W_hh_b = (const float*)d_in[7];
    const float* b_b    = (const float*)d_in[8];
    const float* W_fin  = (const float*)d_in[9];
    const float* b_fin  = (const float*)d_in[10];
    float* out = (float*)d_out;

    prep_kernel<<<2, 256>>>(W_enc, b_enc, W_ih_f, W_hh_f, b_f, W_ih_b, W_hh_b, b_b);
    pad_kernel<<<1, 32>>>();
    pad_kernel<<<1, 32>>>();
    lstm_kernel<<<128, 256>>>(c);
    final_kernel<<<1, 256>>>(W_fin, b_fin, out);
}

// round 7
// speedup vs baseline: 1.4264x; 1.0804x over previous
#include <cuda_runtime.h>
#include <cstdint>
#include <cstddef>

// ---------------------------------------------------------------------------
// Bidirectional LSTM. 512 seqs (256 batch x 2 dirs), 4 per CTA, 128 CTAs.
//
// Round 7 = Round 6 with the stage1 weight-array bug fixed (we[15] -> we[30]).
//   Wh group (warps 8-15, 256 thr): thread = 2 gate rows x 32-h k-half.
//   Wx group (warps 0-7, 256 thr): stage2 gx(n) = W_ih.enc(n)+b;
//     stage1 enc(n+2) = W_enc.x(n+2)+b_enc; x loader 4 steps ahead.
// ---------------------------------------------------------------------------

#define T_STEPS 4096
#define HID     64
#define KIN     60
#define ENC     32
#define NGATES  256

__device__ float g_cfin[2][256][HID];

__device__ __forceinline__ unsigned long long pack2(float lo, float hi) {
    unsigned long long u;
    asm("mov.b64 %0, {%1, %2};" : "=l"(u) : "f"(lo), "f"(hi));
    return u;
}
__device__ __forceinline__ void unpack2(unsigned long long u, float& lo, float& hi) {
    asm("mov.b64 {%0, %1}, %2;" : "=f"(lo), "=f"(hi) : "l"(u));
}
__device__ __forceinline__ void ffma2(unsigned long long& d,
                                      unsigned long long a,
                                      unsigned long long b) {
    asm("fma.rn.f32x2 %0, %1, %2, %0;" : "+l"(d) : "l"(a), "l"(b));
}
__device__ __forceinline__ float fast_sigmoid(float x) {
    return __fdividef(1.0f, 1.0f + __expf(-x));
}
__device__ __forceinline__ float fast_tanh(float x) {
    return 1.0f - __fdividef(2.0f, __expf(2.0f * x) + 1.0f);
}

#define BSYNC(id, cnt) asm volatile("bar.sync %0, %1;"   :: "r"(id), "r"(cnt) : "memory")
#define BARRV(id, cnt) asm volatile("bar.arrive %0, %1;" :: "r"(id), "r"(cnt) : "memory")

__global__ void pad_kernel() {}

// ---------------------------------------------------------------------------
// Named barriers: 1 = Wh h-bar (256); 2/3 = full[slot] (512); 4/5 =
// empty[slot] (512); 6 = Wx internal (256).
// ---------------------------------------------------------------------------
__global__ void __launch_bounds__(512, 1)
lstm_kernel(const float* __restrict__ cin,
            const float* __restrict__ W_enc,  const float* __restrict__ b_enc,
            const float* __restrict__ W_ih_f, const float* __restrict__ W_hh_f,
            const float* __restrict__ b_f,
            const float* __restrict__ W_ih_b, const float* __restrict__ W_hh_b,
            const float* __restrict__ b_b) {
    const int dir = blockIdx.x >> 6;
    const int bg  = blockIdx.x & 63;
    const int tid = threadIdx.x;

    __shared__ __align__(16) float hbuf[4][HID];           // h_t per seq
    __shared__ __align__(16) float xr[3][4][64];           // raw x ring (60 used)
    __shared__ __align__(16) float encr[3][4][ENC];        // encoded x ring
    __shared__ __align__(8)  float gsp[2][4][NGATES];      // Wh.h partials [kh]
    __shared__ __align__(8)  float gxp[2][2][4][NGATES];   // gx ring [slot][kh]

    const float* W_ih = dir ? W_ih_b : W_ih_f;
    const float* W_hh = dir ? W_hh_b : W_hh_f;
    const float* bv   = dir ? b_b    : b_f;

    const bool is_wh = (tid >= 256);
    const int  gid   = tid & 255;
    const int  kh    = gid >> 7;       // k-half
    const int  pr    = gid & 127;
    const int  r0    = 2 * pr;         // 2 gate rows

    const int s_ep = gid >> 6;         // epilogue / h-zero mapping
    const int j_ep = gid & 63;

#define TMAP(t) (dir ? (T_STEPS - 1 - (t)) : (t))

    unsigned long long w0[16], w1[16]; // row weights (Wh: 16 pairs, Wx: 8)
    unsigned long long we[30];         // stage1 encoder weights (30 pairs = 60)
    unsigned long long bi0 = 0ull, bi1 = 0ull;
    float benc = 0.0f;
    float xa = 0.0f;
    const float* cb = nullptr;
    int lseq = 0, lk = 0;
    const int row1 = gid & 31;         // stage1 row
    const int sq1  = gid >> 5;         // stage1 seq (valid for gid<128)

    // ---------------- prologue ----------------
    if (is_wh) {
        const float* a = W_hh + (size_t)r0 * HID + kh * 32;
        const float* b = a + HID;
#pragma unroll
        for (int i = 0; i < 16; i++) {
            float2 p = *reinterpret_cast<const float2*>(a + 2 * i);
            float2 q = *reinterpret_cast<const float2*>(b + 2 * i);
            w0[i] = pack2(p.x, p.y);
            w1[i] = pack2(q.x, q.y);
        }
        hbuf[s_ep][j_ep] = 0.0f;       // h0 = 0
    } else {
        const float* a = W_ih + (size_t)r0 * ENC + kh * 16;
        const float* b = a + ENC;
#pragma unroll
        for (int i = 0; i < 8; i++) {
            float2 p = *reinterpret_cast<const float2*>(a + 2 * i);
            float2 q = *reinterpret_cast<const float2*>(b + 2 * i);
            w0[i] = pack2(p.x, p.y);
            w1[i] = pack2(q.x, q.y);
        }
        if (kh == 0) {                 // bias folded into k-half 0
            bi0 = pack2(bv[r0], 0.0f);
            bi1 = pack2(bv[r0 + 1], 0.0f);
        }
        if (gid < 128) {               // stage1 weights: all 30 pairs
#pragma unroll
            for (int i = 0; i < 30; i++) {
                float2 p = *reinterpret_cast<const float2*>(W_enc + (size_t)row1 * KIN + 2 * i);
                we[i] = pack2(p.x, p.y);
            }
            benc = b_enc[row1];
        }
        if (gid < 240) {               // x loader: 1 element each
            lseq = gid / KIN;
            lk   = gid - lseq * KIN;
            cb   = cin + ((size_t)(bg * 4 + lseq) * T_STEPS) * KIN + lk;
            xr[0][lseq][lk] = __ldg(cb + (size_t)TMAP(0) * KIN);
            xr[1][lseq][lk] = __ldg(cb + (size_t)TMAP(1) * KIN);
            xr[2][lseq][lk] = __ldg(cb + (size_t)TMAP(2) * KIN);
        }
    }
    __syncthreads();

    // prologue stage1: enc(0), enc(1)
    if (!is_wh && gid < 128) {
#pragma unroll
        for (int m = 0; m < 2; m++) {
            unsigned long long acc = 0ull;
            const float* xb = &xr[m][sq1][0];
#pragma unroll
            for (int c = 0; c < 15; c++) {
                const ulonglong2 v = *reinterpret_cast<const ulonglong2*>(xb + 4 * c);
                ffma2(acc, we[2 * c], v.x);
                ffma2(acc, we[2 * c + 1], v.y);
            }
            float l, h;
            unpack2(acc, l, h);
            encr[m][sq1][row1] = benc + l + h;
        }
    }
    if (!is_wh && gid < 240) xa = __ldg(cb + (size_t)TMAP(3) * KIN);
    __syncthreads();

    // ---------------- main loops ----------------
    if (is_wh) {
        float cst = 0.0f;
        for (int t = 0; t < T_STEPS; t++) {
            // Wh . h(t), this k-half: 2 rows x 32 dims x 4 seqs
            unsigned long long a0 = 0ull, a1 = 0ull, a2 = 0ull, a3 = 0ull;
            unsigned long long c0 = 0ull, c1 = 0ull, c2 = 0ull, c3 = 0ull;
            const float* hb = &hbuf[0][0] + kh * 32;
#pragma unroll
            for (int ch = 0; ch < 8; ch++) {
                const ulonglong2 v0 = *reinterpret_cast<const ulonglong2*>(hb + 0 * HID + 4 * ch);
                const ulonglong2 v1 = *reinterpret_cast<const ulonglong2*>(hb + 1 * HID + 4 * ch);
                const ulonglong2 v2 = *reinterpret_cast<const ulonglong2*>(hb + 2 * HID + 4 * ch);
                const ulonglong2 v3 = *reinterpret_cast<const ulonglong2*>(hb + 3 * HID + 4 * ch);
                ffma2(a0, w0[2 * ch], v0.x); ffma2(a0, w0[2 * ch + 1], v0.y);
                ffma2(c0, w1[2 * ch], v0.x); ffma2(c0, w1[2 * ch + 1], v0.y);
                ffma2(a1, w0[2 * ch], v1.x); ffma2(a1, w0[2 * ch + 1], v1.y);
                ffma2(c1, w1[2 * ch], v1.x); ffma2(c1, w1[2 * ch + 1], v1.y);
                ffma2(a2, w0[2 * ch], v2.x); ffma2(a2, w0[2 * ch + 1], v2.y);
                ffma2(c2, w1[2 * ch], v2.x); ffma2(c2, w1[2 * ch + 1], v2.y);
                ffma2(a3, w0[2 * ch], v3.x); ffma2(a3, w0[2 * ch + 1], v3.y);
                ffma2(c3, w1[2 * ch], v3.x); ffma2(c3, w1[2 * ch + 1], v3.y);
            }
            {
                float l, h, l2, h2;
                unpack2(a0, l, h); unpack2(c0, l2, h2);
                *reinterpret_cast<float2*>(&gsp[kh][0][r0]) = make_float2(l + h, l2 + h2);
                unpack2(a1, l, h); unpack2(c1, l2, h2);
                *reinterpret_cast<float2*>(&gsp[kh][1][r0]) = make_float2(l + h, l2 + h2);
                unpack2(a2, l, h); unpack2(c2, l2, h2);
                *reinterpret_cast<float2*>(&gsp[kh][2][r0]) = make_float2(l + h, l2 + h2);
                unpack2(a3, l, h); unpack2(c3, l2, h2);
                *reinterpret_cast<float2*>(&gsp[kh][3][r0]) = make_float2(l + h, l2 + h2);
            }
            // full[t&1]: gx(t) ready (Wx arrived) AND all Wh gsp STS drained
            BSYNC(2 + (t & 1), 512);

            // epilogue: 1 cell per thread
            {
                const int   sl = t & 1;
                const float gi = gsp[0][s_ep][j_ep] + gsp[1][s_ep][j_ep]
                               + gxp[sl][0][s_ep][j_ep] + gxp[sl][1][s_ep][j_ep];
                const float gf = gsp[0][s_ep][64 + j_ep] + gsp[1][s_ep][64 + j_ep]
                               + gxp[sl][0][s_ep][64 + j_ep] + gxp[sl][1][s_ep][64 + j_ep];
                const float gg = gsp[0][s_ep][128 + j_ep] + gsp[1][s_ep][128 + j_ep]
                               + gxp[sl][0][s_ep][128 + j_ep] + gxp[sl][1][s_ep][128 + j_ep];
                const float go = gsp[0][s_ep][192 + j_ep] + gsp[1][s_ep][192 + j_ep]
                               + gxp[sl][0][s_ep][192 + j_ep] + gxp[sl][1][s_ep][192 + j_ep];

                const float ig = fast_sigmoid(gi);
                const float fg = fast_sigmoid(gf);
                const float og = fast_sigmoid(go);
                const float gt = fast_tanh(gg);
                cst = fg * cst + ig * gt;
                hbuf[s_ep][j_ep] = og * fast_tanh(cst);
            }
            BARRV(4 + (t & 1), 512);   // empty[t&1]: gx slot consumed
            BSYNC(1, 256);             // h(t+1) published within Wh group
        }
        g_cfin[dir][bg * 4 + s_ep][j_ep] = cst;
    } else {
        int m3 = 0;                    // n % 3
        for (int n = 0; n < T_STEPS; n++) {
            if (n >= 2) BSYNC(4 + (n & 1), 512);   // empty[n&1]

            // stage2: gx(n) partials = W_ih[.,khalf] . enc(n) (+bias on kh0)
            {
                unsigned long long a0 = bi0, a1 = bi0, a2 = bi0, a3 = bi0;
                unsigned long long c0 = bi1, c1 = bi1, c2 = bi1, c3 = bi1;
                const float* eb = &encr[m3][0][0] + kh * 16;
#pragma unroll
                for (int ch = 0; ch < 4; ch++) {
                    const ulonglong2 v0 = *reinterpret_cast<const ulonglong2*>(eb + 0 * ENC + 4 * ch);
                    const ulonglong2 v1 = *reinterpret_cast<const ulonglong2*>(eb + 1 * ENC + 4 * ch);
                    const ulonglong2 v2 = *reinterpret_cast<const ulonglong2*>(eb + 2 * ENC + 4 * ch);
                    const ulonglong2 v3 = *reinterpret_cast<const ulonglong2*>(eb + 3 * ENC + 4 * ch);
                    ffma2(a0, w0[2 * ch], v0.x); ffma2(a0, w0[2 * ch + 1], v0.y);
                    ffma2(c0, w1[2 * ch], v0.x); ffma2(c0, w1[2 * ch + 1], v0.y);
                    ffma2(a1, w0[2 * ch], v1.x); ffma2(a1, w0[2 * ch + 1], v1.y);
                    ffma2(c1, w1[2 * ch], v1.x); ffma2(c1, w1[2 * ch + 1], v1.y);
                    ffma2(a2, w0[2 * ch], v2.x); ffma2(a2, w0[2 * ch + 1], v2.y);
                    ffma2(c2, w1[2 * ch], v2.x); ffma2(c2, w1[2 * ch + 1], v2.y);
                    ffma2(a3, w0[2 * ch], v3.x); ffma2(a3, w0[2 * ch + 1], v3.y);
                    ffma2(c3, w1[2 * ch], v3.x); ffma2(c3, w1[2 * ch + 1], v3.y);
                }
                const int gs = n & 1;
                float l, h, l2, h2;
                unpack2(a0, l, h); unpack2(c0, l2, h2);
                *reinterpret_cast<float2*>(&gxp[gs][kh][0][r0]) = make_float2(l + h, l2 + h2);
                unpack2(a1, l, h); unpack2(c1, l2, h2);
                *reinterpret_cast<float2*>(&gxp[gs][kh][1][r0]) = make_float2(l + h, l2 + h2);
                unpack2(a2, l, h); unpack2(c2, l2, h2);
                *reinterpret_cast<float2*>(&gxp[gs][kh][2][r0]) = make_float2(l + h, l2 + h2);
                unpack2(a3, l, h); unpack2(c3, l2, h2);
                *reinterpret_cast<float2*>(&gxp[gs][kh][3][r0]) = make_float2(l + h, l2 + h2);
            }
            BARRV(2 + (n & 1), 512);   // full[n&1]: gx(n) published
            BSYNC(6, 256);             // Wx internal: encr/xr reads retired

            // stage1: enc(n+2) from xr[(n+2)%3] -> encr[(n+2)%3]
            const int sl2 = (m3 + 2 >= 3) ? (m3 - 1) : (m3 + 2);   // (n+2)%3
            if (gid < 128 && (n + 2) < T_STEPS) {
                unsigned long long acc = 0ull;
                const float* xb = &xr[sl2][sq1][0];
#pragma unroll
                for (int c = 0; c < 15; c++) {
                    const ulonglong2 v = *reinterpret_cast<const ulonglong2*>(xb + 4 * c);
                    ffma2(acc, we[2 * c], v.x);
                    ffma2(acc, we[2 * c + 1], v.y);
                }
                float l, h;
                unpack2(acc, l, h);
                encr[sl2][sq1][row1] = benc + l + h;
            }
            // loader: stage x(n+3) into xr[n%3]; LDG x(n+4)
            if (gid < 240) {
                if (n + 3 < T_STEPS) xr[m3][lseq][lk] = xa;
                if (n + 4 < T_STEPS) xa = __ldg(cb + (size_t)TMAP(n + 4) * KIN);
            }
            m3 = (m3 == 2) ? 0 : m3 + 1;
        }
    }
}

// ---------------------------------------------------------------------------
__global__ void final_kernel(const float* __restrict__ W_fin,
                             const float* __restrict__ b_fin,
                             float* __restrict__ out) {
    const int b = threadIdx.x;
    float a0 = b_fin[0], a1 = b_fin[1], a2 = b_fin[2];
#pragma unroll
    for (int j = 0; j < HID; j++) {
        const float cf = g_cfin[0][b][j];
        a0 += W_fin[0 * 128 + j] * cf;
        a1 += W_fin[1 * 128 + j] * cf;
        a2 += W_fin[2 * 128 + j] * cf;
    }
#pragma unroll
    for (int j = 0; j < HID; j++) {
        const float cb = g_cfin[1][b][j];
        a0 += W_fin[0 * 128 + 64 + j] * cb;
        a1 += W_fin[1 * 128 + 64 + j] * cb;
        a2 += W_fin[2 * 128 + 64 + j] * cb;
    }
    out[b * 3 + 0] = a0;
    out[b * 3 + 1] = a1;
    out[b * 3 + 2] = a2;
}

extern "C" void kernel_launch(void* const* d_in, const int* in_sizes, int n_in,
                              void* d_out, int out_size) {
    (void)in_sizes; (void)n_in; (void)out_size;
    const float* c      = (const float*)d_in[0];
    const float* W_enc  = (const float*)d_in[1];
    const float* b_enc  = (const float*)d_in[2];
    const float* W_ih_f = (const float*)d_in[3];
    const float* W_hh_f = (const float*)d_in[4];
    const float* b_f    = (const float*)d_in[5];
    const float* W_ih_b = (const float*)d_in[6];
    const float* W_hh_b = (const float*)d_in[7];
    const float* b_b    = (const float*)d_in[8];
    const float* W_fin  = (const float*)d_in[9];
    const float* b_fin  = (const float*)d_in[10];
    float* out = (float*)d_out;

    // 3 pads keep ncu -s 5 -c 1 aligned on lstm_kernel
    pad_kernel<<<1, 32>>>();
    pad_kernel<<<1, 32>>>();
    pad_kernel<<<1, 32>>>();
    lstm_kernel<<<128, 512>>>(c, W_enc, b_enc,
                              W_ih_f, W_hh_f, b_f,
                              W_ih_b, W_hh_b, b_b);
    final_kernel<<<1, 256>>>(W_fin, b_fin, out);
}